// round 6
// baseline (speedup 1.0000x reference)
#include <cuda_runtime.h>
#include <cuda_bf16.h>
#include <cstdint>

#define B_    64
#define S_    512
#define H_    1024
#define HID_  512
#define K3_   3072   // 3*H
#define EPS_  1e-5f
#define NCHUNK 8     // row chunks per span pass (512/64)
#define CHROWS 64    // rows per chunk
#define KC_   48     // k per smem tile
#define NSLAB 32     // gemm k-slabs (each CTA covers 2*KC_ = 96 k)

// Scratch (device globals: allocation-free)
__device__ float g_sp[B_ * 2 * NCHUNK * H_];   // span partial sums      (4 MB)
__device__ float g_x [B_ * K3_];               // concat embeddings      (768 KB)
__device__ float g_hp[NSLAB * B_ * HID_];      // GEMM partial slabs     (4 MB)
__device__ float g_hd[B_ * 4 * 3];             // head partial dots

// ---------------------------------------------------------------------------
// Inline offset decode: detect int64 vs int32 source.
// Must be called by ALL threads of the block (contains __syncthreads).
// ---------------------------------------------------------------------------
__device__ __forceinline__ int off_not64(const unsigned int* __restrict__ raw) {
    __shared__ int flag;
    if (threadIdx.x == 0) flag = 0;
    __syncthreads();
    for (int t = threadIdx.x; t < 160; t += blockDim.x)
        if (raw[2 * t + 1] != 0u) atomicExch(&flag, 1);
    __syncthreads();
    return flag;
}
__device__ __forceinline__ int off_get(const unsigned int* __restrict__ raw,
                                       int not64, int idx) {
    return not64 ? (int)raw[idx] : (int)raw[2 * idx];
}

// ---------------------------------------------------------------------------
// Kernel 1: fused span partial sums (both spans in ONE pass over each row).
// grid (B, NCHUNK), 256 thr, float4/thread. Rows in the union are read once.
// ---------------------------------------------------------------------------
__global__ void span_partial(const float* __restrict__ bert,
                             const unsigned int* __restrict__ raw) {
    int n64 = off_not64(raw);
    int b  = blockIdx.x;
    int z  = blockIdx.y;
    int a0 = off_get(raw, n64, b * 5 + 0), a1 = off_get(raw, n64, b * 5 + 1);
    int c0 = off_get(raw, n64, b * 5 + 2), c1 = off_get(raw, n64, b * 5 + 3);
    int lo = z * CHROWS, hi = lo + CHROWS - 1;
    // clip to union bounding range within this chunk
    int u0 = max(lo, min(a0, c0));
    int u1 = min(hi, max(a1, c1));

    int t = threadIdx.x;
    float4 accA = make_float4(0.f, 0.f, 0.f, 0.f);
    float4 accB = make_float4(0.f, 0.f, 0.f, 0.f);
    const float* base = bert + ((size_t)b * S_) * H_ + 4 * t;
    #pragma unroll 4
    for (int s = u0; s <= u1; ++s) {
        bool inA = (s >= a0) & (s <= a1);
        bool inB = (s >= c0) & (s <= c1);
        if (inA | inB) {
            float4 v = *(const float4*)(base + (size_t)s * H_);
            float fa = inA ? 1.f : 0.f;
            float fb = inB ? 1.f : 0.f;
            accA.x = fmaf(v.x, fa, accA.x); accA.y = fmaf(v.y, fa, accA.y);
            accA.z = fmaf(v.z, fa, accA.z); accA.w = fmaf(v.w, fa, accA.w);
            accB.x = fmaf(v.x, fb, accB.x); accB.y = fmaf(v.y, fb, accB.y);
            accB.z = fmaf(v.z, fb, accB.z); accB.w = fmaf(v.w, fb, accB.w);
        }
    }
    float* dA = g_sp + ((size_t)((b * 2 + 0) * NCHUNK + z)) * H_ + 4 * t;
    float* dB = g_sp + ((size_t)((b * 2 + 1) * NCHUNK + z)) * H_ + 4 * t;
    *(float4*)dA = accA;
    *(float4*)dB = accB;
}

// ---------------------------------------------------------------------------
// Kernel 2: reduce chunks -> means, gather pronoun row. grid(B), 1024 thr.
// ---------------------------------------------------------------------------
__global__ void finalize_x(const float* __restrict__ bert,
                           const unsigned int* __restrict__ raw) {
    int n64 = off_not64(raw);
    int b = blockIdx.x;
    int h = threadIdx.x;
    int a0 = off_get(raw, n64, b * 5 + 0), a1 = off_get(raw, n64, b * 5 + 1);
    int c0 = off_get(raw, n64, b * 5 + 2), c1 = off_get(raw, n64, b * 5 + 3);
    int p  = off_get(raw, n64, b * 5 + 4);
    float inva = 1.0f / (float)(a1 - a0 + 1);
    float invb = 1.0f / (float)(c1 - c0 + 1);

    float sa = 0.f, sb = 0.f;
    #pragma unroll
    for (int z = 0; z < NCHUNK; ++z) {
        sa += g_sp[((size_t)((b * 2 + 0) * NCHUNK + z)) * H_ + h];
        sb += g_sp[((size_t)((b * 2 + 1) * NCHUNK + z)) * H_ + h];
    }
    float* xr = g_x + (size_t)b * K3_;
    xr[h]            = sa * inva;
    xr[H_ + h]       = sb * invb;
    xr[2 * H_ + h]   = bert[((size_t)b * S_ + p) * H_ + h];
}

// ---------------------------------------------------------------------------
// Kernel 3: GEMM x(64x3072) @ W1(3072x512) -> NSLAB partial slabs (64x512).
// grid(4 jt x 32 kt2) = 128 CTAs (single wave), 256 threads.
// Each CTA: two 48-k passes through smem, acc kept in registers.
// Thread tile 4m x 8j, FFMA2, register double-buffered inner loop.
// ---------------------------------------------------------------------------
#define FMA2(A, W, X) asm("fma.rn.f32x2 %0, %1, %2, %0;" \
                          : "+l"(A) : "l"(W), "l"(X))

__global__ void __launch_bounds__(256) gemm1(const float* __restrict__ W1) {
    __shared__ float  ws[KC_ * 128];            // 24 KB  [k][j]
    __shared__ float2 xs2[KC_ * 64];            // 24 KB  [k][m] duplicated

    int jt  = blockIdx.x;           // 0..3
    int kt2 = blockIdx.y;           // 0..31
    int tid = threadIdx.x;
    int jg  = tid & 15;             // 16 j-groups of 8
    int mg  = tid >> 4;             // 16 m-groups of 4
    int jb  = jt * 128;
    int m0  = mg * 4;
    int j0  = jg * 8;

    unsigned long long acc[4][4];   // [m][j-pair]
    #pragma unroll
    for (int m = 0; m < 4; ++m)
        #pragma unroll
        for (int q = 0; q < 4; ++q) acc[m][q] = 0ull;

    const float*  wp = ws + j0;
    const float2* xp = xs2 + m0;

    #pragma unroll
    for (int pass = 0; pass < 2; ++pass) {
        int k0 = (kt2 * 2 + pass) * KC_;
        if (pass) __syncthreads();   // smem reuse fence

        // W1 tile [KC_][128]: coalesced LDG.128, conflict-free STS
        #pragma unroll
        for (int it = 0; it < 6; ++it) {
            int i = it * 256 + tid;
            int r = i >> 5, c = (i & 31) << 2;
            *(float4*)&ws[r * 128 + c] =
                *(const float4*)&W1[(size_t)(k0 + r) * HID_ + jb + c];
        }
        // x tile transposed + duplicated {v,v}: conflict-free STS
        #pragma unroll
        for (int it = 0; it < 3; ++it) {
            int i  = it * 256 + tid;
            int kq = i >> 6;
            int m  = i & 63;
            float4 v = *(const float4*)&g_x[(size_t)m * K3_ + k0 + kq * 4];
            xs2[(kq * 4 + 0) * 64 + m] = make_float2(v.x, v.x);
            xs2[(kq * 4 + 1) * 64 + m] = make_float2(v.y, v.y);
            xs2[(kq * 4 + 2) * 64 + m] = make_float2(v.z, v.z);
            xs2[(kq * 4 + 3) * 64 + m] = make_float2(v.w, v.w);
        }
        __syncthreads();

        // register double-buffer: prefetch k+1 while FMA'ing k
        ulonglong2 cwa = *(const ulonglong2*)(wp);
        ulonglong2 cwb = *(const ulonglong2*)(wp + 4);
        ulonglong2 cxa = *(const ulonglong2*)(xp);
        ulonglong2 cxb = *(const ulonglong2*)(xp + 2);

        #pragma unroll
        for (int k = 0; k < KC_; ++k) {
            ulonglong2 nwa, nwb, nxa, nxb;
            if (k < KC_ - 1) {
                const float*  wn = wp + (k + 1) * 128;
                const float2* xn = xp + (k + 1) * 64;
                nwa = *(const ulonglong2*)(wn);
                nwb = *(const ulonglong2*)(wn + 4);
                nxa = *(const ulonglong2*)(xn);
                nxb = *(const ulonglong2*)(xn + 2);
            }
            unsigned long long w0 = cwa.x, w1 = cwa.y, w2 = cwb.x, w3 = cwb.y;
            unsigned long long x0 = cxa.x, x1 = cxa.y, x2 = cxb.x, x3 = cxb.y;
            FMA2(acc[0][0], w0, x0); FMA2(acc[0][1], w1, x0);
            FMA2(acc[0][2], w2, x0); FMA2(acc[0][3], w3, x0);
            FMA2(acc[1][0], w0, x1); FMA2(acc[1][1], w1, x1);
            FMA2(acc[1][2], w2, x1); FMA2(acc[1][3], w3, x1);
            FMA2(acc[2][0], w0, x2); FMA2(acc[2][1], w1, x2);
            FMA2(acc[2][2], w2, x2); FMA2(acc[2][3], w3, x2);
            FMA2(acc[3][0], w0, x3); FMA2(acc[3][1], w1, x3);
            FMA2(acc[3][2], w2, x3); FMA2(acc[3][3], w3, x3);
            cwa = nwa; cwb = nwb; cxa = nxa; cxb = nxb;
        }
    }

    float* dst = g_hp + (size_t)kt2 * B_ * HID_;
    #pragma unroll
    for (int m = 0; m < 4; ++m) {
        unsigned long long* row =
            (unsigned long long*)&dst[(size_t)(m0 + m) * HID_ + jb + j0];
        row[0] = acc[m][0];
        row[1] = acc[m][1];
        row[2] = acc[m][2];
        row[3] = acc[m][3];
    }
}

// ---------------------------------------------------------------------------
// Kernel 4a: reduce NSLAB slabs, BN + leaky, partial W2 dots.
// grid(B_, 4), 128 threads (one j each) -> g_hd[b][jq][3].
// ---------------------------------------------------------------------------
__global__ void head_partial(const float* __restrict__ b1,
                             const float* __restrict__ gamma,
                             const float* __restrict__ beta,
                             const float* __restrict__ rmean,
                             const float* __restrict__ rvar,
                             const float* __restrict__ W2) {
    int b  = blockIdx.x;
    int jq = blockIdx.y;
    int t  = threadIdx.x;              // 0..127
    int j  = jq * 128 + t;

    float s = 0.f;
    #pragma unroll
    for (int p = 0; p < NSLAB; ++p)
        s += g_hp[(size_t)p * B_ * HID_ + (size_t)b * HID_ + j];

    float sc = gamma[j] * rsqrtf(rvar[j] + EPS_);
    float h  = (s + b1[j] - rmean[j]) * sc + beta[j];
    h = (h >= 0.f) ? h : 0.01f * h;

    float o0 = h * W2[j * 3 + 0];
    float o1 = h * W2[j * 3 + 1];
    float o2 = h * W2[j * 3 + 2];

    #pragma unroll
    for (int d = 16; d > 0; d >>= 1) {
        o0 += __shfl_down_sync(0xFFFFFFFFu, o0, d);
        o1 += __shfl_down_sync(0xFFFFFFFFu, o1, d);
        o2 += __shfl_down_sync(0xFFFFFFFFu, o2, d);
    }
    __shared__ float red[4][3];
    if ((t & 31) == 0) {
        int w = t >> 5;
        red[w][0] = o0; red[w][1] = o1; red[w][2] = o2;
    }
    __syncthreads();
    if (t < 3) {
        float v = red[0][t] + red[1][t] + red[2][t] + red[3][t];
        g_hd[(b * 4 + jq) * 3 + t] = v;
    }
}

// ---------------------------------------------------------------------------
// Kernel 4b: final sum of 4 partials + b2 -> out[64][3]. One block.
// ---------------------------------------------------------------------------
__global__ void head_final(const float* __restrict__ b2,
                           float* __restrict__ out) {
    int i = threadIdx.x;               // 0..191
    if (i < B_ * 3) {
        int b = i / 3, d = i % 3;
        float v = b2[d];
        #pragma unroll
        for (int q = 0; q < 4; ++q) v += g_hd[(b * 4 + q) * 3 + d];
        out[i] = v;
    }
}

// ---------------------------------------------------------------------------
extern "C" void kernel_launch(void* const* d_in, const int* in_sizes, int n_in,
                              void* d_out, int out_size) {
    const float*        bert  = (const float*)d_in[0];
    const unsigned int* offw  = (const unsigned int*)d_in[1];
    const float*        W1    = (const float*)d_in[2];
    const float*        b1    = (const float*)d_in[3];
    const float*        gamma = (const float*)d_in[4];
    const float*        beta  = (const float*)d_in[5];
    const float*        rmean = (const float*)d_in[6];
    const float*        rvar  = (const float*)d_in[7];
    const float*        W2    = (const float*)d_in[8];
    const float*        b2    = (const float*)d_in[9];
    float* out = (float*)d_out;

    span_partial<<<dim3(B_, NCHUNK), 256>>>(bert, offw);
    finalize_x<<<B_, 1024>>>(bert, offw);
    gemm1<<<dim3(4, NSLAB), 256>>>(W1);
    head_partial<<<dim3(B_, 4), 128>>>(b1, gamma, beta, rmean, rvar, W2);
    head_final<<<1, 192>>>(b2, out);
}

// round 7
// speedup vs baseline: 1.0483x; 1.0483x over previous
#include <cuda_runtime.h>
#include <cuda_bf16.h>
#include <cstdint>

#define B_    64
#define S_    512
#define H_    1024
#define HID_  512
#define K3_   3072   // 3*H
#define EPS_  1e-5f
#define NCHUNK 8     // row chunks per span pass (512/64)
#define CHROWS 64    // rows per chunk
#define KC_   48     // k per smem tile
#define NSLAB 64     // gemm k-slabs (one per kt)

// Scratch (device globals: allocation-free)
__device__ float g_sp[B_ * 2 * NCHUNK * H_];   // span partial sums      (4 MB)
__device__ float g_x [B_ * K3_];               // concat embeddings      (768 KB)
__device__ float g_hp[NSLAB * B_ * HID_];      // GEMM partial slabs     (8 MB)
__device__ float g_hd[B_ * 4 * 3];             // head partial dots

// ---------------------------------------------------------------------------
// Inline offset decode: detect int64 vs int32 source.
// Must be called by ALL threads of the block (contains __syncthreads).
// ---------------------------------------------------------------------------
__device__ __forceinline__ int off_not64(const unsigned int* __restrict__ raw) {
    __shared__ int flag;
    if (threadIdx.x == 0) flag = 0;
    __syncthreads();
    for (int t = threadIdx.x; t < 160; t += blockDim.x)
        if (raw[2 * t + 1] != 0u) atomicExch(&flag, 1);
    __syncthreads();
    return flag;
}
__device__ __forceinline__ int off_get(const unsigned int* __restrict__ raw,
                                       int not64, int idx) {
    return not64 ? (int)raw[idx] : (int)raw[2 * idx];
}

// ---------------------------------------------------------------------------
// Kernel 1: fused span partial sums (both spans in ONE pass over each row).
// grid (B, NCHUNK), 256 thr, float4/thread. Rows in the union are read once.
// ---------------------------------------------------------------------------
__global__ void span_partial(const float* __restrict__ bert,
                             const unsigned int* __restrict__ raw) {
    int n64 = off_not64(raw);
    int b  = blockIdx.x;
    int z  = blockIdx.y;
    int a0 = off_get(raw, n64, b * 5 + 0), a1 = off_get(raw, n64, b * 5 + 1);
    int c0 = off_get(raw, n64, b * 5 + 2), c1 = off_get(raw, n64, b * 5 + 3);
    int lo = z * CHROWS, hi = lo + CHROWS - 1;
    int u0 = max(lo, min(a0, c0));
    int u1 = min(hi, max(a1, c1));

    int t = threadIdx.x;
    float4 accA = make_float4(0.f, 0.f, 0.f, 0.f);
    float4 accB = make_float4(0.f, 0.f, 0.f, 0.f);
    const float* base = bert + ((size_t)b * S_) * H_ + 4 * t;
    #pragma unroll 4
    for (int s = u0; s <= u1; ++s) {
        bool inA = (s >= a0) & (s <= a1);
        bool inB = (s >= c0) & (s <= c1);
        if (inA | inB) {
            float4 v = *(const float4*)(base + (size_t)s * H_);
            float fa = inA ? 1.f : 0.f;
            float fb = inB ? 1.f : 0.f;
            accA.x = fmaf(v.x, fa, accA.x); accA.y = fmaf(v.y, fa, accA.y);
            accA.z = fmaf(v.z, fa, accA.z); accA.w = fmaf(v.w, fa, accA.w);
            accB.x = fmaf(v.x, fb, accB.x); accB.y = fmaf(v.y, fb, accB.y);
            accB.z = fmaf(v.z, fb, accB.z); accB.w = fmaf(v.w, fb, accB.w);
        }
    }
    float* dA = g_sp + ((size_t)((b * 2 + 0) * NCHUNK + z)) * H_ + 4 * t;
    float* dB = g_sp + ((size_t)((b * 2 + 1) * NCHUNK + z)) * H_ + 4 * t;
    *(float4*)dA = accA;
    *(float4*)dB = accB;
}

// ---------------------------------------------------------------------------
// Kernel 2: reduce chunks -> means, gather pronoun row. grid(B), 1024 thr.
// ---------------------------------------------------------------------------
__global__ void finalize_x(const float* __restrict__ bert,
                           const unsigned int* __restrict__ raw) {
    int n64 = off_not64(raw);
    int b = blockIdx.x;
    int h = threadIdx.x;
    int a0 = off_get(raw, n64, b * 5 + 0), a1 = off_get(raw, n64, b * 5 + 1);
    int c0 = off_get(raw, n64, b * 5 + 2), c1 = off_get(raw, n64, b * 5 + 3);
    int p  = off_get(raw, n64, b * 5 + 4);
    float inva = 1.0f / (float)(a1 - a0 + 1);
    float invb = 1.0f / (float)(c1 - c0 + 1);

    float sa = 0.f, sb = 0.f;
    #pragma unroll
    for (int z = 0; z < NCHUNK; ++z) {
        sa += g_sp[((size_t)((b * 2 + 0) * NCHUNK + z)) * H_ + h];
        sb += g_sp[((size_t)((b * 2 + 1) * NCHUNK + z)) * H_ + h];
    }
    float* xr = g_x + (size_t)b * K3_;
    xr[h]            = sa * inva;
    xr[H_ + h]       = sb * invb;
    xr[2 * H_ + h]   = bert[((size_t)b * S_ + p) * H_ + h];
}

// ---------------------------------------------------------------------------
// Kernel 3: GEMM x(64x3072) @ W1(3072x512) -> NSLAB partial slabs (64x512).
// grid(4 jt x 64 kt), 512 threads. Block tile 64m x 128j x 48k.
// Thread tile 4m x 4j (16 warps/CTA for latency coverage), FFMA2,
// register double-buffered inner loop.
// ---------------------------------------------------------------------------
#define FMA2(A, W, X) asm("fma.rn.f32x2 %0, %1, %2, %0;" \
                          : "+l"(A) : "l"(W), "l"(X))

__global__ void __launch_bounds__(512) gemm1(const float* __restrict__ W1) {
    __shared__ float  ws[KC_ * 128];            // 24 KB  [k][j]
    __shared__ float2 xs2[KC_ * 64];            // 24 KB  [k][m] duplicated

    int jt  = blockIdx.x;           // 0..3
    int kt  = blockIdx.y;           // 0..63
    int tid = threadIdx.x;
    int jg  = tid & 31;             // 32 j-groups of 4
    int mg  = tid >> 5;             // 16 m-groups of 4
    int jb  = jt * 128;
    int k0  = kt * KC_;
    int j0  = jg * 4;
    int m0  = mg * 4;

    // W1 tile [KC_][128]: coalesced LDG.128, conflict-free STS
    #pragma unroll
    for (int it = 0; it < 3; ++it) {
        int i = it * 512 + tid;                 // 0 .. 1535
        int r = i >> 5, c = (i & 31) << 2;
        *(float4*)&ws[r * 128 + c] =
            *(const float4*)&W1[(size_t)(k0 + r) * HID_ + jb + c];
    }
    // x tile transposed + duplicated {v,v}: conflict-free STS
    for (int i = tid; i < 768; i += 512) {
        int kq = i >> 6;                        // 0..11
        int m  = i & 63;
        float4 v = *(const float4*)&g_x[(size_t)m * K3_ + k0 + kq * 4];
        xs2[(kq * 4 + 0) * 64 + m] = make_float2(v.x, v.x);
        xs2[(kq * 4 + 1) * 64 + m] = make_float2(v.y, v.y);
        xs2[(kq * 4 + 2) * 64 + m] = make_float2(v.z, v.z);
        xs2[(kq * 4 + 3) * 64 + m] = make_float2(v.w, v.w);
    }
    __syncthreads();

    unsigned long long acc[4][2];   // [m][j-pair]
    #pragma unroll
    for (int m = 0; m < 4; ++m) {
        acc[m][0] = 0ull; acc[m][1] = 0ull;
    }

    const float*  wp = ws + j0;
    const float2* xp = xs2 + m0;

    // register double-buffer: prefetch k+1 while FMA'ing k
    ulonglong2 cw  = *(const ulonglong2*)(wp);
    ulonglong2 cxa = *(const ulonglong2*)(xp);
    ulonglong2 cxb = *(const ulonglong2*)(xp + 2);

    #pragma unroll
    for (int k = 0; k < KC_; ++k) {
        ulonglong2 nw, nxa, nxb;
        if (k < KC_ - 1) {
            nw  = *(const ulonglong2*)(wp + (k + 1) * 128);
            nxa = *(const ulonglong2*)(xp + (k + 1) * 64);
            nxb = *(const ulonglong2*)(xp + (k + 1) * 64 + 2);
        }
        unsigned long long w0 = cw.x, w1 = cw.y;
        unsigned long long x0 = cxa.x, x1 = cxa.y, x2 = cxb.x, x3 = cxb.y;
        FMA2(acc[0][0], w0, x0); FMA2(acc[0][1], w1, x0);
        FMA2(acc[1][0], w0, x1); FMA2(acc[1][1], w1, x1);
        FMA2(acc[2][0], w0, x2); FMA2(acc[2][1], w1, x2);
        FMA2(acc[3][0], w0, x3); FMA2(acc[3][1], w1, x3);
        cw = nw; cxa = nxa; cxb = nxb;
    }

    float* dst = g_hp + (size_t)kt * B_ * HID_;
    #pragma unroll
    for (int m = 0; m < 4; ++m) {
        unsigned long long* row =
            (unsigned long long*)&dst[(size_t)(m0 + m) * HID_ + jb + j0];
        row[0] = acc[m][0];
        row[1] = acc[m][1];
    }
}

// ---------------------------------------------------------------------------
// Kernel 4a: reduce NSLAB slabs (float4, MLP=8/thread), BN + leaky,
// partial W2 dots. grid(B_, 4), 256 threads -> g_hd[b][jq][3].
// Thread (jg, pg): jg = j-quad 0..31, pg = slab-group 0..7 (8 slabs each).
// ---------------------------------------------------------------------------
__global__ void __launch_bounds__(256) head_partial(
        const float* __restrict__ b1,
        const float* __restrict__ gamma,
        const float* __restrict__ beta,
        const float* __restrict__ rmean,
        const float* __restrict__ rvar,
        const float* __restrict__ W2) {
    int b  = blockIdx.x;
    int jq = blockIdx.y;
    int t  = threadIdx.x;              // 0..255
    int jg = t & 31;                   // j-quad index
    int pg = t >> 5;                   // slab group 0..7
    int j  = jq * 128 + jg * 4;

    const float* src = g_hp + (size_t)b * HID_ + j;
    float4 s = make_float4(0.f, 0.f, 0.f, 0.f);
    #pragma unroll
    for (int p = 0; p < 8; ++p) {
        float4 v = *(const float4*)(src + (size_t)(pg * 8 + p) * B_ * HID_);
        s.x += v.x; s.y += v.y; s.z += v.z; s.w += v.w;
    }
    __shared__ float4 red[8][32];
    red[pg][jg] = s;
    __syncthreads();

    float o0 = 0.f, o1 = 0.f, o2 = 0.f;
    if (t < 32) {
        float4 h4 = red[0][t];
        #pragma unroll
        for (int p = 1; p < 8; ++p) {
            float4 v = red[p][t];
            h4.x += v.x; h4.y += v.y; h4.z += v.z; h4.w += v.w;
        }
        int jj = jq * 128 + t * 4;
        float hv[4] = {h4.x, h4.y, h4.z, h4.w};
        #pragma unroll
        for (int c = 0; c < 4; ++c) {
            int jc = jj + c;
            float sc = gamma[jc] * rsqrtf(rvar[jc] + EPS_);
            float h  = (hv[c] + b1[jc] - rmean[jc]) * sc + beta[jc];
            h = (h >= 0.f) ? h : 0.01f * h;
            o0 = fmaf(h, W2[jc * 3 + 0], o0);
            o1 = fmaf(h, W2[jc * 3 + 1], o1);
            o2 = fmaf(h, W2[jc * 3 + 2], o2);
        }
        #pragma unroll
        for (int d = 16; d > 0; d >>= 1) {
            o0 += __shfl_down_sync(0xFFFFFFFFu, o0, d);
            o1 += __shfl_down_sync(0xFFFFFFFFu, o1, d);
            o2 += __shfl_down_sync(0xFFFFFFFFu, o2, d);
        }
        if (t == 0) {
            g_hd[(b * 4 + jq) * 3 + 0] = o0;
            g_hd[(b * 4 + jq) * 3 + 1] = o1;
            g_hd[(b * 4 + jq) * 3 + 2] = o2;
        }
    }
}

// ---------------------------------------------------------------------------
// Kernel 4b: final sum of 4 partials + b2 -> out[64][3]. One block.
// ---------------------------------------------------------------------------
__global__ void head_final(const float* __restrict__ b2,
                           float* __restrict__ out) {
    int i = threadIdx.x;               // 0..191
    if (i < B_ * 3) {
        int b = i / 3, d = i % 3;
        float v = b2[d];
        #pragma unroll
        for (int q = 0; q < 4; ++q) v += g_hd[(b * 4 + q) * 3 + d];
        out[i] = v;
    }
}

// ---------------------------------------------------------------------------
extern "C" void kernel_launch(void* const* d_in, const int* in_sizes, int n_in,
                              void* d_out, int out_size) {
    const float*        bert  = (const float*)d_in[0];
    const unsigned int* offw  = (const unsigned int*)d_in[1];
    const float*        W1    = (const float*)d_in[2];
    const float*        b1    = (const float*)d_in[3];
    const float*        gamma = (const float*)d_in[4];
    const float*        beta  = (const float*)d_in[5];
    const float*        rmean = (const float*)d_in[6];
    const float*        rvar  = (const float*)d_in[7];
    const float*        W2    = (const float*)d_in[8];
    const float*        b2    = (const float*)d_in[9];
    float* out = (float*)d_out;

    span_partial<<<dim3(B_, NCHUNK), 256>>>(bert, offw);
    finalize_x<<<B_, 1024>>>(bert, offw);
    gemm1<<<dim3(4, NSLAB), 512>>>(W1);
    head_partial<<<dim3(B_, 4), 256>>>(b1, gamma, beta, rmean, rvar, W2);
    head_final<<<1, 192>>>(b2, out);
}

// round 8
// speedup vs baseline: 1.3144x; 1.2538x over previous
#include <cuda_runtime.h>
#include <cuda_bf16.h>
#include <cstdint>

#define B_    64
#define S_    512
#define H_    1024
#define HID_  512
#define K3_   3072   // 3*H
#define EPS_  1e-5f
#define NCHUNK 8     // row chunks per span pass (512/64)
#define CHROWS 64    // rows per chunk
#define KC_   48     // k per smem tile
#define NSLAB 64     // gemm k-slabs (one per kt)

// Scratch (device globals: allocation-free)
__device__ float g_sp[B_ * 2 * NCHUNK * H_];   // span partial sums      (4 MB)
__device__ float g_x [B_ * K3_];               // concat embeddings      (768 KB)
__device__ float g_hp[NSLAB * B_ * HID_];      // GEMM partial slabs     (8 MB)
__device__ float g_hd[B_ * 4 * 3];             // head partial dots

// ---------------------------------------------------------------------------
// Inline offset decode: detect int64 vs int32 source.
// ---------------------------------------------------------------------------
__device__ __forceinline__ int off_not64(const unsigned int* __restrict__ raw) {
    __shared__ int flag;
    if (threadIdx.x == 0) flag = 0;
    __syncthreads();
    for (int t = threadIdx.x; t < 160; t += blockDim.x)
        if (raw[2 * t + 1] != 0u) atomicExch(&flag, 1);
    __syncthreads();
    return flag;
}
__device__ __forceinline__ int off_get(const unsigned int* __restrict__ raw,
                                       int not64, int idx) {
    return not64 ? (int)raw[idx] : (int)raw[2 * idx];
}

// ---------------------------------------------------------------------------
// Kernel 1: span partial sums, branch-free. Two ranges per block: span A rows
// then span B rows (overlap re-read comes from L2). grid (B, NCHUNK), 256 thr.
// ---------------------------------------------------------------------------
__global__ void span_partial(const float* __restrict__ bert,
                             const unsigned int* __restrict__ raw) {
    int n64 = off_not64(raw);
    int b  = blockIdx.x;
    int z  = blockIdx.y;
    int a0 = off_get(raw, n64, b * 5 + 0), a1 = off_get(raw, n64, b * 5 + 1);
    int c0 = off_get(raw, n64, b * 5 + 2), c1 = off_get(raw, n64, b * 5 + 3);
    int lo = z * CHROWS, hi = lo + CHROWS - 1;
    int sA0 = max(a0, lo), sA1 = min(a1, hi);
    int sB0 = max(c0, lo), sB1 = min(c1, hi);

    int t = threadIdx.x;
    const float* base = bert + ((size_t)b * S_) * H_ + 4 * t;

    float4 accA = make_float4(0.f, 0.f, 0.f, 0.f);
    #pragma unroll 4
    for (int s = sA0; s <= sA1; ++s) {
        float4 v = *(const float4*)(base + (size_t)s * H_);
        accA.x += v.x; accA.y += v.y; accA.z += v.z; accA.w += v.w;
    }
    float4 accB = make_float4(0.f, 0.f, 0.f, 0.f);
    #pragma unroll 4
    for (int s = sB0; s <= sB1; ++s) {
        float4 v = *(const float4*)(base + (size_t)s * H_);
        accB.x += v.x; accB.y += v.y; accB.z += v.z; accB.w += v.w;
    }
    float* dA = g_sp + ((size_t)((b * 2 + 0) * NCHUNK + z)) * H_ + 4 * t;
    float* dB = g_sp + ((size_t)((b * 2 + 1) * NCHUNK + z)) * H_ + 4 * t;
    *(float4*)dA = accA;
    *(float4*)dB = accB;
}

// ---------------------------------------------------------------------------
// Kernel 2: reduce chunks -> means, gather pronoun row. grid(B), 1024 thr.
// ---------------------------------------------------------------------------
__global__ void finalize_x(const float* __restrict__ bert,
                           const unsigned int* __restrict__ raw) {
    int n64 = off_not64(raw);
    int b = blockIdx.x;
    int h = threadIdx.x;
    int a0 = off_get(raw, n64, b * 5 + 0), a1 = off_get(raw, n64, b * 5 + 1);
    int c0 = off_get(raw, n64, b * 5 + 2), c1 = off_get(raw, n64, b * 5 + 3);
    int p  = off_get(raw, n64, b * 5 + 4);
    float inva = 1.0f / (float)(a1 - a0 + 1);
    float invb = 1.0f / (float)(c1 - c0 + 1);

    float sa = 0.f, sb = 0.f;
    #pragma unroll
    for (int z = 0; z < NCHUNK; ++z) {
        sa += g_sp[((size_t)((b * 2 + 0) * NCHUNK + z)) * H_ + h];
        sb += g_sp[((size_t)((b * 2 + 1) * NCHUNK + z)) * H_ + h];
    }
    float* xr = g_x + (size_t)b * K3_;
    xr[h]            = sa * inva;
    xr[H_ + h]       = sb * invb;
    xr[2 * H_ + h]   = bert[((size_t)b * S_ + p) * H_ + h];
}

// ---------------------------------------------------------------------------
// Kernel 3: GEMM x(64x3072) @ W1(3072x512) -> NSLAB partial slabs (64x512).
// grid(2 jt x 64 kt) = 128 CTAs, 256 threads. Block tile 64m x 256j x 48k.
// Thread tile 8m x 8j (j-pairs spread at stride 64 -> conflict-free LDS.64);
// x warp-uniform broadcast. 32 FFMA2 per thread-k -> FMA-pipe bound.
// ---------------------------------------------------------------------------
#define FMA2(A, W, X) asm("fma.rn.f32x2 %0, %1, %2, %0;" \
                          : "+l"(A) : "l"(W), "l"(X))

__global__ void __launch_bounds__(256) gemm1(const float* __restrict__ W1) {
    extern __shared__ char smraw[];
    float2* xs2 = (float2*)smraw;                    // [KC_][64]  24 KB
    float*  ws  = (float*)(smraw + KC_ * 64 * 8);    // [KC_][256] 48 KB

    int jt  = blockIdx.x;           // 0..1
    int kt  = blockIdx.y;           // 0..63
    int tid = threadIdx.x;
    int jg  = tid & 31;             // lane: j-pair base
    int mg  = tid >> 5;             // warp: m-group of 8
    int jb  = jt * 256;
    int k0  = kt * KC_;
    int m0  = mg * 8;

    // W1 tile [KC_][256]: 3072 float4 / 256 thr = 12 iters, coalesced LDG,
    // conflict-free STS.
    #pragma unroll
    for (int it = 0; it < 12; ++it) {
        int i = it * 256 + tid;
        int r = i >> 6, c = (i & 63) << 2;
        *(float4*)&ws[r * 256 + c] =
            *(const float4*)&W1[(size_t)(k0 + r) * HID_ + jb + c];
    }
    // x tile transposed + duplicated {v,v}: conflict-free STS.
    #pragma unroll
    for (int it = 0; it < 3; ++it) {
        int i  = it * 256 + tid;
        int kq = i >> 6;                        // 0..11
        int m  = i & 63;
        float4 v = *(const float4*)&g_x[(size_t)m * K3_ + k0 + kq * 4];
        xs2[(kq * 4 + 0) * 64 + m] = make_float2(v.x, v.x);
        xs2[(kq * 4 + 1) * 64 + m] = make_float2(v.y, v.y);
        xs2[(kq * 4 + 2) * 64 + m] = make_float2(v.z, v.z);
        xs2[(kq * 4 + 3) * 64 + m] = make_float2(v.w, v.w);
    }
    __syncthreads();

    unsigned long long acc[8][4];   // [m][q]  j = jb + 2*jg + 64*q
    #pragma unroll
    for (int m = 0; m < 8; ++m)
        #pragma unroll
        for (int q = 0; q < 4; ++q) acc[m][q] = 0ull;

    const float*  wp = ws + 2 * jg;
    const float2* xp = xs2 + m0;

    // register double-buffer
    unsigned long long cw[4];
    ulonglong2 cx[4];
    #pragma unroll
    for (int q = 0; q < 4; ++q)
        cw[q] = *(const unsigned long long*)(wp + q * 64);
    #pragma unroll
    for (int i = 0; i < 4; ++i)
        cx[i] = *(const ulonglong2*)(xp + i * 2);

    #pragma unroll
    for (int k = 0; k < KC_; ++k) {
        unsigned long long nw[4];
        ulonglong2 nx[4];
        if (k < KC_ - 1) {
            const float*  wn = wp + (k + 1) * 256;
            const float2* xn = xp + (k + 1) * 64;
            #pragma unroll
            for (int q = 0; q < 4; ++q)
                nw[q] = *(const unsigned long long*)(wn + q * 64);
            #pragma unroll
            for (int i = 0; i < 4; ++i)
                nx[i] = *(const ulonglong2*)(xn + i * 2);
        }
        unsigned long long xm[8] = {cx[0].x, cx[0].y, cx[1].x, cx[1].y,
                                    cx[2].x, cx[2].y, cx[3].x, cx[3].y};
        #pragma unroll
        for (int m = 0; m < 8; ++m) {
            FMA2(acc[m][0], cw[0], xm[m]);
            FMA2(acc[m][1], cw[1], xm[m]);
            FMA2(acc[m][2], cw[2], xm[m]);
            FMA2(acc[m][3], cw[3], xm[m]);
        }
        #pragma unroll
        for (int q = 0; q < 4; ++q) cw[q] = nw[q];
        #pragma unroll
        for (int i = 0; i < 4; ++i) cx[i] = nx[i];
    }

    float* dst = g_hp + (size_t)kt * B_ * HID_;
    #pragma unroll
    for (int m = 0; m < 8; ++m)
        #pragma unroll
        for (int q = 0; q < 4; ++q)
            *(unsigned long long*)
                &dst[(size_t)(m0 + m) * HID_ + jb + 2 * jg + 64 * q] =
                acc[m][q];
}

// ---------------------------------------------------------------------------
// Kernel 4a: reduce NSLAB slabs (float4, MLP=8/thread), BN + leaky,
// partial W2 dots. grid(B_, 4), 256 threads -> g_hd[b][jq][3].
// ---------------------------------------------------------------------------
__global__ void __launch_bounds__(256) head_partial(
        const float* __restrict__ b1,
        const float* __restrict__ gamma,
        const float* __restrict__ beta,
        const float* __restrict__ rmean,
        const float* __restrict__ rvar,
        const float* __restrict__ W2) {
    int b  = blockIdx.x;
    int jq = blockIdx.y;
    int t  = threadIdx.x;              // 0..255
    int jg = t & 31;                   // j-quad index
    int pg = t >> 5;                   // slab group 0..7
    int j  = jq * 128 + jg * 4;

    const float* src = g_hp + (size_t)b * HID_ + j;
    float4 s = make_float4(0.f, 0.f, 0.f, 0.f);
    #pragma unroll
    for (int p = 0; p < 8; ++p) {
        float4 v = *(const float4*)(src + (size_t)(pg * 8 + p) * B_ * HID_);
        s.x += v.x; s.y += v.y; s.z += v.z; s.w += v.w;
    }
    __shared__ float4 red[8][32];
    red[pg][jg] = s;
    __syncthreads();

    if (t < 32) {
        float4 h4 = red[0][t];
        #pragma unroll
        for (int p = 1; p < 8; ++p) {
            float4 v = red[p][t];
            h4.x += v.x; h4.y += v.y; h4.z += v.z; h4.w += v.w;
        }
        int jj = jq * 128 + t * 4;
        float hv[4] = {h4.x, h4.y, h4.z, h4.w};
        float o0 = 0.f, o1 = 0.f, o2 = 0.f;
        #pragma unroll
        for (int c = 0; c < 4; ++c) {
            int jc = jj + c;
            float sc = gamma[jc] * rsqrtf(rvar[jc] + EPS_);
            float h  = (hv[c] + b1[jc] - rmean[jc]) * sc + beta[jc];
            h = (h >= 0.f) ? h : 0.01f * h;
            o0 = fmaf(h, W2[jc * 3 + 0], o0);
            o1 = fmaf(h, W2[jc * 3 + 1], o1);
            o2 = fmaf(h, W2[jc * 3 + 2], o2);
        }
        #pragma unroll
        for (int d = 16; d > 0; d >>= 1) {
            o0 += __shfl_down_sync(0xFFFFFFFFu, o0, d);
            o1 += __shfl_down_sync(0xFFFFFFFFu, o1, d);
            o2 += __shfl_down_sync(0xFFFFFFFFu, o2, d);
        }
        if (t == 0) {
            g_hd[(b * 4 + jq) * 3 + 0] = o0;
            g_hd[(b * 4 + jq) * 3 + 1] = o1;
            g_hd[(b * 4 + jq) * 3 + 2] = o2;
        }
    }
}

// ---------------------------------------------------------------------------
// Kernel 4b: final sum of 4 partials + b2 -> out[64][3]. One block.
// ---------------------------------------------------------------------------
__global__ void head_final(const float* __restrict__ b2,
                           float* __restrict__ out) {
    int i = threadIdx.x;               // 0..191
    if (i < B_ * 3) {
        int b = i / 3, d = i % 3;
        float v = b2[d];
        #pragma unroll
        for (int q = 0; q < 4; ++q) v += g_hd[(b * 4 + q) * 3 + d];
        out[i] = v;
    }
}

// ---------------------------------------------------------------------------
extern "C" void kernel_launch(void* const* d_in, const int* in_sizes, int n_in,
                              void* d_out, int out_size) {
    const float*        bert  = (const float*)d_in[0];
    const unsigned int* offw  = (const unsigned int*)d_in[1];
    const float*        W1    = (const float*)d_in[2];
    const float*        b1    = (const float*)d_in[3];
    const float*        gamma = (const float*)d_in[4];
    const float*        beta  = (const float*)d_in[5];
    const float*        rmean = (const float*)d_in[6];
    const float*        rvar  = (const float*)d_in[7];
    const float*        W2    = (const float*)d_in[8];
    const float*        b2    = (const float*)d_in[9];
    float* out = (float*)d_out;

    const int gemm_smem = KC_ * 64 * 8 + KC_ * 256 * 4;  // 24 KB + 48 KB
    cudaFuncSetAttribute(gemm1, cudaFuncAttributeMaxDynamicSharedMemorySize,
                         gemm_smem);

    span_partial<<<dim3(B_, NCHUNK), 256>>>(bert, offw);
    finalize_x<<<B_, 1024>>>(bert, offw);
    gemm1<<<dim3(2, NSLAB), 256, gemm_smem>>>(W1);
    head_partial<<<dim3(B_, 4), 256>>>(b1, gamma, beta, rmean, rvar, W2);
    head_final<<<1, 192>>>(b2, out);
}

// round 9
// speedup vs baseline: 1.3892x; 1.0569x over previous
#include <cuda_runtime.h>
#include <cuda_bf16.h>
#include <cstdint>

#define B_    64
#define S_    512
#define H_    1024
#define HID_  512
#define K3_   3072   // 3*H
#define EPS_  1e-5f
#define NCHUNK 8     // row chunks per span pass (512/64)
#define CHROWS 64    // rows per chunk
#define KC_   48     // k per smem tile
#define NSLAB 64     // gemm k-slabs (one per kt)

// Scratch (device globals: allocation-free)
__device__ float g_sp[B_ * 2 * NCHUNK * H_];   // span partial sums      (4 MB)
__device__ float g_x [B_ * K3_];               // concat embeddings      (768 KB)
__device__ float g_h [B_ * HID_];              // GEMM accumulator       (128 KB)

// ---------------------------------------------------------------------------
// Inline offset decode: detect int64 vs int32 source.
// ---------------------------------------------------------------------------
__device__ __forceinline__ int off_not64(const unsigned int* __restrict__ raw) {
    __shared__ int flag;
    if (threadIdx.x == 0) flag = 0;
    __syncthreads();
    for (int t = threadIdx.x; t < 160; t += blockDim.x)
        if (raw[2 * t + 1] != 0u) atomicExch(&flag, 1);
    __syncthreads();
    return flag;
}
__device__ __forceinline__ int off_get(const unsigned int* __restrict__ raw,
                                       int not64, int idx) {
    return not64 ? (int)raw[idx] : (int)raw[2 * idx];
}

// ---------------------------------------------------------------------------
// Kernel 1: span partial sums, branch-free. Two ranges per block: span A rows
// then span B rows (overlap re-read comes from L2). grid (B, NCHUNK), 256 thr.
// ---------------------------------------------------------------------------
__global__ void span_partial(const float* __restrict__ bert,
                             const unsigned int* __restrict__ raw) {
    int n64 = off_not64(raw);
    int b  = blockIdx.x;
    int z  = blockIdx.y;
    int a0 = off_get(raw, n64, b * 5 + 0), a1 = off_get(raw, n64, b * 5 + 1);
    int c0 = off_get(raw, n64, b * 5 + 2), c1 = off_get(raw, n64, b * 5 + 3);
    int lo = z * CHROWS, hi = lo + CHROWS - 1;
    int sA0 = max(a0, lo), sA1 = min(a1, hi);
    int sB0 = max(c0, lo), sB1 = min(c1, hi);

    int t = threadIdx.x;
    const float* base = bert + ((size_t)b * S_) * H_ + 4 * t;

    float4 accA = make_float4(0.f, 0.f, 0.f, 0.f);
    #pragma unroll 4
    for (int s = sA0; s <= sA1; ++s) {
        float4 v = *(const float4*)(base + (size_t)s * H_);
        accA.x += v.x; accA.y += v.y; accA.z += v.z; accA.w += v.w;
    }
    float4 accB = make_float4(0.f, 0.f, 0.f, 0.f);
    #pragma unroll 4
    for (int s = sB0; s <= sB1; ++s) {
        float4 v = *(const float4*)(base + (size_t)s * H_);
        accB.x += v.x; accB.y += v.y; accB.z += v.z; accB.w += v.w;
    }
    float* dA = g_sp + ((size_t)((b * 2 + 0) * NCHUNK + z)) * H_ + 4 * t;
    float* dB = g_sp + ((size_t)((b * 2 + 1) * NCHUNK + z)) * H_ + 4 * t;
    *(float4*)dA = accA;
    *(float4*)dB = accB;
}

// ---------------------------------------------------------------------------
// Kernel 2: reduce chunks -> means, gather pronoun row, zero g_h.
// grid(B), 1024 thr.
// ---------------------------------------------------------------------------
__global__ void finalize_x(const float* __restrict__ bert,
                           const unsigned int* __restrict__ raw) {
    int n64 = off_not64(raw);
    int b = blockIdx.x;
    int h = threadIdx.x;
    int a0 = off_get(raw, n64, b * 5 + 0), a1 = off_get(raw, n64, b * 5 + 1);
    int c0 = off_get(raw, n64, b * 5 + 2), c1 = off_get(raw, n64, b * 5 + 3);
    int p  = off_get(raw, n64, b * 5 + 4);
    float inva = 1.0f / (float)(a1 - a0 + 1);
    float invb = 1.0f / (float)(c1 - c0 + 1);

    float sa = 0.f, sb = 0.f;
    #pragma unroll
    for (int z = 0; z < NCHUNK; ++z) {
        sa += g_sp[((size_t)((b * 2 + 0) * NCHUNK + z)) * H_ + h];
        sb += g_sp[((size_t)((b * 2 + 1) * NCHUNK + z)) * H_ + h];
    }
    float* xr = g_x + (size_t)b * K3_;
    xr[h]            = sa * inva;
    xr[H_ + h]       = sb * invb;
    xr[2 * H_ + h]   = bert[((size_t)b * S_ + p) * H_ + h];

    if (h < HID_) g_h[b * HID_ + h] = 0.f;   // zero the REDG accumulator
}

// ---------------------------------------------------------------------------
// Kernel 3: GEMM x(64x3072) @ W1(3072x512), split-k over 64 kt chunks.
// grid(2 jt x 64 kt) = 128 CTAs, 256 threads. Block tile 64m x 256j x 48k.
// Thread tile 8m x 8j, FFMA2, x broadcast, conflict-free LDS.64 for W.
// Epilogue: RED.E.ADD.F32 directly into g_h (no slab round-trip).
// ---------------------------------------------------------------------------
#define FMA2(A, W, X) asm("fma.rn.f32x2 %0, %1, %2, %0;" \
                          : "+l"(A) : "l"(W), "l"(X))

__global__ void __launch_bounds__(256) gemm1(const float* __restrict__ W1) {
    extern __shared__ char smraw[];
    float2* xs2 = (float2*)smraw;                    // [KC_][64]  24 KB
    float*  ws  = (float*)(smraw + KC_ * 64 * 8);    // [KC_][256] 48 KB

    int jt  = blockIdx.x;           // 0..1
    int kt  = blockIdx.y;           // 0..63
    int tid = threadIdx.x;
    int jg  = tid & 31;             // lane: j-pair base
    int mg  = tid >> 5;             // warp: m-group of 8
    int jb  = jt * 256;
    int k0  = kt * KC_;
    int m0  = mg * 8;

    // W1 tile [KC_][256]: coalesced LDG.128, conflict-free STS
    #pragma unroll
    for (int it = 0; it < 12; ++it) {
        int i = it * 256 + tid;
        int r = i >> 6, c = (i & 63) << 2;
        *(float4*)&ws[r * 256 + c] =
            *(const float4*)&W1[(size_t)(k0 + r) * HID_ + jb + c];
    }
    // x tile transposed + duplicated {v,v}: conflict-free STS
    #pragma unroll
    for (int it = 0; it < 3; ++it) {
        int i  = it * 256 + tid;
        int kq = i >> 6;                        // 0..11
        int m  = i & 63;
        float4 v = *(const float4*)&g_x[(size_t)m * K3_ + k0 + kq * 4];
        xs2[(kq * 4 + 0) * 64 + m] = make_float2(v.x, v.x);
        xs2[(kq * 4 + 1) * 64 + m] = make_float2(v.y, v.y);
        xs2[(kq * 4 + 2) * 64 + m] = make_float2(v.z, v.z);
        xs2[(kq * 4 + 3) * 64 + m] = make_float2(v.w, v.w);
    }
    __syncthreads();

    unsigned long long acc[8][4];   // [m][q]  j = jb + 2*jg + 64*q
    #pragma unroll
    for (int m = 0; m < 8; ++m)
        #pragma unroll
        for (int q = 0; q < 4; ++q) acc[m][q] = 0ull;

    const float*  wp = ws + 2 * jg;
    const float2* xp = xs2 + m0;

    // register double-buffer
    unsigned long long cw[4];
    ulonglong2 cx[4];
    #pragma unroll
    for (int q = 0; q < 4; ++q)
        cw[q] = *(const unsigned long long*)(wp + q * 64);
    #pragma unroll
    for (int i = 0; i < 4; ++i)
        cx[i] = *(const ulonglong2*)(xp + i * 2);

    #pragma unroll
    for (int k = 0; k < KC_; ++k) {
        unsigned long long nw[4];
        ulonglong2 nx[4];
        if (k < KC_ - 1) {
            const float*  wn = wp + (k + 1) * 256;
            const float2* xn = xp + (k + 1) * 64;
            #pragma unroll
            for (int q = 0; q < 4; ++q)
                nw[q] = *(const unsigned long long*)(wn + q * 64);
            #pragma unroll
            for (int i = 0; i < 4; ++i)
                nx[i] = *(const ulonglong2*)(xn + i * 2);
        }
        unsigned long long xm[8] = {cx[0].x, cx[0].y, cx[1].x, cx[1].y,
                                    cx[2].x, cx[2].y, cx[3].x, cx[3].y};
        #pragma unroll
        for (int m = 0; m < 8; ++m) {
            FMA2(acc[m][0], cw[0], xm[m]);
            FMA2(acc[m][1], cw[1], xm[m]);
            FMA2(acc[m][2], cw[2], xm[m]);
            FMA2(acc[m][3], cw[3], xm[m]);
        }
        #pragma unroll
        for (int q = 0; q < 4; ++q) cw[q] = nw[q];
        #pragma unroll
        for (int i = 0; i < 4; ++i) cx[i] = nx[i];
    }

    // Epilogue: no-return atomics into g_h (RED.E.ADD.F32, spread addresses)
    #pragma unroll
    for (int m = 0; m < 8; ++m) {
        float* row = &g_h[(m0 + m) * HID_ + jb + 2 * jg];
        #pragma unroll
        for (int q = 0; q < 4; ++q) {
            float2 v = *(float2*)&acc[m][q];
            atomicAdd(row + 64 * q,     v.x);
            atomicAdd(row + 64 * q + 1, v.y);
        }
    }
}

// ---------------------------------------------------------------------------
// Kernel 4: BN + leaky + @W2 + b2 -> out[64][3]. grid(B), 512 thr (L2-hot).
// ---------------------------------------------------------------------------
__global__ void head(const float* __restrict__ b1,
                     const float* __restrict__ gamma,
                     const float* __restrict__ beta,
                     const float* __restrict__ rmean,
                     const float* __restrict__ rvar,
                     const float* __restrict__ W2,
                     const float* __restrict__ b2,
                     float* __restrict__ out) {
    int b = blockIdx.x;
    int j = threadIdx.x;               // 0..511

    float s  = g_h[b * HID_ + j];
    float sc = gamma[j] * rsqrtf(rvar[j] + EPS_);
    float h  = (s + b1[j] - rmean[j]) * sc + beta[j];
    h = (h >= 0.f) ? h : 0.01f * h;

    float o0 = h * W2[j * 3 + 0];
    float o1 = h * W2[j * 3 + 1];
    float o2 = h * W2[j * 3 + 2];

    #pragma unroll
    for (int d = 16; d > 0; d >>= 1) {
        o0 += __shfl_down_sync(0xFFFFFFFFu, o0, d);
        o1 += __shfl_down_sync(0xFFFFFFFFu, o1, d);
        o2 += __shfl_down_sync(0xFFFFFFFFu, o2, d);
    }

    __shared__ float red[16][3];
    if ((j & 31) == 0) {
        int w = j >> 5;
        red[w][0] = o0; red[w][1] = o1; red[w][2] = o2;
    }
    __syncthreads();
    if (j < 3) {
        float t = 0.f;
        #pragma unroll
        for (int w = 0; w < 16; ++w) t += red[w][j];
        out[b * 3 + j] = t + b2[j];
    }
}

// ---------------------------------------------------------------------------
extern "C" void kernel_launch(void* const* d_in, const int* in_sizes, int n_in,
                              void* d_out, int out_size) {
    const float*        bert  = (const float*)d_in[0];
    const unsigned int* offw  = (const unsigned int*)d_in[1];
    const float*        W1    = (const float*)d_in[2];
    const float*        b1    = (const float*)d_in[3];
    const float*        gamma = (const float*)d_in[4];
    const float*        beta  = (const float*)d_in[5];
    const float*        rmean = (const float*)d_in[6];
    const float*        rvar  = (const float*)d_in[7];
    const float*        W2    = (const float*)d_in[8];
    const float*        b2    = (const float*)d_in[9];
    float* out = (float*)d_out;

    const int gemm_smem = KC_ * 64 * 8 + KC_ * 256 * 4;  // 24 KB + 48 KB
    cudaFuncSetAttribute(gemm1, cudaFuncAttributeMaxDynamicSharedMemorySize,
                         gemm_smem);

    span_partial<<<dim3(B_, NCHUNK), 256>>>(bert, offw);
    finalize_x<<<B_, 1024>>>(bert, offw);
    gemm1<<<dim3(2, NSLAB), 256, gemm_smem>>>(W1);
    head<<<B_, 512>>>(b1, gamma, beta, rmean, rvar, W2, b2, out);
}

// round 10
// speedup vs baseline: 1.4875x; 1.0707x over previous
#include <cuda_runtime.h>
#include <cuda_bf16.h>
#include <cstdint>

#define B_    64
#define S_    512
#define H_    1024
#define HID_  512
#define K3_   3072   // 3*H
#define EPS_  1e-5f
#define NCHUNK 8     // row chunks per span pass (512/64)
#define CHROWS 64    // rows per chunk
#define KC_   48     // k per smem tile
#define NSLAB 64     // gemm k-slabs (one per kt)

// Scratch (device globals: allocation-free, zero-initialized at load).
// INVARIANT: g_x and g_h are all-zero on entry to kernel_launch; the head
// kernel restores this invariant at the end of every call.
__device__ float g_x[B_ * K3_];                // concat embeddings      (768 KB)
__device__ float g_h[B_ * HID_];               // GEMM accumulator       (128 KB)

// ---------------------------------------------------------------------------
// Inline offset decode: detect int64 vs int32 source.
// ---------------------------------------------------------------------------
__device__ __forceinline__ int off_not64(const unsigned int* __restrict__ raw) {
    __shared__ int flag;
    if (threadIdx.x == 0) flag = 0;
    __syncthreads();
    for (int t = threadIdx.x; t < 160; t += blockDim.x)
        if (raw[2 * t + 1] != 0u) atomicExch(&flag, 1);
    __syncthreads();
    return flag;
}
__device__ __forceinline__ int off_get(const unsigned int* __restrict__ raw,
                                       int not64, int idx) {
    return not64 ? (int)raw[idx] : (int)raw[2 * idx];
}

// ---------------------------------------------------------------------------
// Kernel 1: span partial means -> REDG into g_x; pronoun row copy.
// grid (B, NCHUNK), 256 thr, float4/thread. Two clipped ranges per block.
// ---------------------------------------------------------------------------
__global__ void span_partial(const float* __restrict__ bert,
                             const unsigned int* __restrict__ raw) {
    int n64 = off_not64(raw);
    int b  = blockIdx.x;
    int z  = blockIdx.y;
    int a0 = off_get(raw, n64, b * 5 + 0), a1 = off_get(raw, n64, b * 5 + 1);
    int c0 = off_get(raw, n64, b * 5 + 2), c1 = off_get(raw, n64, b * 5 + 3);
    int p  = off_get(raw, n64, b * 5 + 4);
    int lo = z * CHROWS, hi = lo + CHROWS - 1;
    int sA0 = max(a0, lo), sA1 = min(a1, hi);
    int sB0 = max(c0, lo), sB1 = min(c1, hi);
    float inva = 1.0f / (float)(a1 - a0 + 1);
    float invb = 1.0f / (float)(c1 - c0 + 1);

    int t = threadIdx.x;
    const float* base = bert + ((size_t)b * S_) * H_ + 4 * t;
    float* xr = g_x + (size_t)b * K3_ + 4 * t;

    if (sA1 >= sA0) {
        float4 acc = make_float4(0.f, 0.f, 0.f, 0.f);
        #pragma unroll 4
        for (int s = sA0; s <= sA1; ++s) {
            float4 v = *(const float4*)(base + (size_t)s * H_);
            acc.x += v.x; acc.y += v.y; acc.z += v.z; acc.w += v.w;
        }
        atomicAdd(xr + 0, acc.x * inva);
        atomicAdd(xr + 1, acc.y * inva);
        atomicAdd(xr + 2, acc.z * inva);
        atomicAdd(xr + 3, acc.w * inva);
    }
    if (sB1 >= sB0) {
        float4 acc = make_float4(0.f, 0.f, 0.f, 0.f);
        #pragma unroll 4
        for (int s = sB0; s <= sB1; ++s) {
            float4 v = *(const float4*)(base + (size_t)s * H_);
            acc.x += v.x; acc.y += v.y; acc.z += v.z; acc.w += v.w;
        }
        atomicAdd(xr + H_ + 0, acc.x * invb);
        atomicAdd(xr + H_ + 1, acc.y * invb);
        atomicAdd(xr + H_ + 2, acc.z * invb);
        atomicAdd(xr + H_ + 3, acc.w * invb);
    }
    // Pronoun row: the chunk that owns row p copies it (plain stores).
    if (p >= lo && p <= hi) {
        float4 v = *(const float4*)(base + (size_t)p * H_);
        *(float4*)(xr + 2 * H_) = v;
    }
}

// ---------------------------------------------------------------------------
// Kernel 2: GEMM x(64x3072) @ W1(3072x512), split-k over 64 kt chunks.
// grid(2 jt x 64 kt) = 128 CTAs, 256 threads. Block tile 64m x 256j x 48k.
// Thread tile 8m x 8j, FFMA2, x broadcast, conflict-free LDS.64 for W.
// Epilogue: RED.E.ADD.F32 into g_h.
// ---------------------------------------------------------------------------
#define FMA2(A, W, X) asm("fma.rn.f32x2 %0, %1, %2, %0;" \
                          : "+l"(A) : "l"(W), "l"(X))

__global__ void __launch_bounds__(256) gemm1(const float* __restrict__ W1) {
    extern __shared__ char smraw[];
    float2* xs2 = (float2*)smraw;                    // [KC_][64]  24 KB
    float*  ws  = (float*)(smraw + KC_ * 64 * 8);    // [KC_][256] 48 KB

    int jt  = blockIdx.x;           // 0..1
    int kt  = blockIdx.y;           // 0..63
    int tid = threadIdx.x;
    int jg  = tid & 31;             // lane: j-pair base
    int mg  = tid >> 5;             // warp: m-group of 8
    int jb  = jt * 256;
    int k0  = kt * KC_;
    int m0  = mg * 8;

    // W1 tile [KC_][256]: coalesced LDG.128, conflict-free STS
    #pragma unroll
    for (int it = 0; it < 12; ++it) {
        int i = it * 256 + tid;
        int r = i >> 6, c = (i & 63) << 2;
        *(float4*)&ws[r * 256 + c] =
            *(const float4*)&W1[(size_t)(k0 + r) * HID_ + jb + c];
    }
    // x tile transposed + duplicated {v,v}: conflict-free STS
    #pragma unroll
    for (int it = 0; it < 3; ++it) {
        int i  = it * 256 + tid;
        int kq = i >> 6;                        // 0..11
        int m  = i & 63;
        float4 v = *(const float4*)&g_x[(size_t)m * K3_ + k0 + kq * 4];
        xs2[(kq * 4 + 0) * 64 + m] = make_float2(v.x, v.x);
        xs2[(kq * 4 + 1) * 64 + m] = make_float2(v.y, v.y);
        xs2[(kq * 4 + 2) * 64 + m] = make_float2(v.z, v.z);
        xs2[(kq * 4 + 3) * 64 + m] = make_float2(v.w, v.w);
    }
    __syncthreads();

    unsigned long long acc[8][4];   // [m][q]  j = jb + 2*jg + 64*q
    #pragma unroll
    for (int m = 0; m < 8; ++m)
        #pragma unroll
        for (int q = 0; q < 4; ++q) acc[m][q] = 0ull;

    const float*  wp = ws + 2 * jg;
    const float2* xp = xs2 + m0;

    // register double-buffer
    unsigned long long cw[4];
    ulonglong2 cx[4];
    #pragma unroll
    for (int q = 0; q < 4; ++q)
        cw[q] = *(const unsigned long long*)(wp + q * 64);
    #pragma unroll
    for (int i = 0; i < 4; ++i)
        cx[i] = *(const ulonglong2*)(xp + i * 2);

    #pragma unroll
    for (int k = 0; k < KC_; ++k) {
        unsigned long long nw[4];
        ulonglong2 nx[4];
        if (k < KC_ - 1) {
            const float*  wn = wp + (k + 1) * 256;
            const float2* xn = xp + (k + 1) * 64;
            #pragma unroll
            for (int q = 0; q < 4; ++q)
                nw[q] = *(const unsigned long long*)(wn + q * 64);
            #pragma unroll
            for (int i = 0; i < 4; ++i)
                nx[i] = *(const ulonglong2*)(xn + i * 2);
        }
        unsigned long long xm[8] = {cx[0].x, cx[0].y, cx[1].x, cx[1].y,
                                    cx[2].x, cx[2].y, cx[3].x, cx[3].y};
        #pragma unroll
        for (int m = 0; m < 8; ++m) {
            FMA2(acc[m][0], cw[0], xm[m]);
            FMA2(acc[m][1], cw[1], xm[m]);
            FMA2(acc[m][2], cw[2], xm[m]);
            FMA2(acc[m][3], cw[3], xm[m]);
        }
        #pragma unroll
        for (int q = 0; q < 4; ++q) cw[q] = nw[q];
        #pragma unroll
        for (int i = 0; i < 4; ++i) cx[i] = nx[i];
    }

    // Epilogue: no-return atomics into g_h (spread addresses)
    #pragma unroll
    for (int m = 0; m < 8; ++m) {
        float* row = &g_h[(m0 + m) * HID_ + jb + 2 * jg];
        #pragma unroll
        for (int q = 0; q < 4; ++q) {
            float2 v = *(float2*)&acc[m][q];
            atomicAdd(row + 64 * q,     v.x);
            atomicAdd(row + 64 * q + 1, v.y);
        }
    }
}

// ---------------------------------------------------------------------------
// Kernel 3: BN + leaky + @W2 + b2 -> out[64][3]; then restore the zero
// invariant on g_h (same thread that read it) and g_x (block-partitioned).
// grid(B), 512 thr.
// ---------------------------------------------------------------------------
__global__ void head(const float* __restrict__ b1,
                     const float* __restrict__ gamma,
                     const float* __restrict__ beta,
                     const float* __restrict__ rmean,
                     const float* __restrict__ rvar,
                     const float* __restrict__ W2,
                     const float* __restrict__ b2,
                     float* __restrict__ out) {
    int b = blockIdx.x;
    int j = threadIdx.x;               // 0..511

    float s  = g_h[b * HID_ + j];
    g_h[b * HID_ + j] = 0.f;           // re-zero own element (same thread)

    float sc = gamma[j] * rsqrtf(rvar[j] + EPS_);
    float h  = (s + b1[j] - rmean[j]) * sc + beta[j];
    h = (h >= 0.f) ? h : 0.01f * h;

    float o0 = h * W2[j * 3 + 0];
    float o1 = h * W2[j * 3 + 1];
    float o2 = h * W2[j * 3 + 2];

    #pragma unroll
    for (int d = 16; d > 0; d >>= 1) {
        o0 += __shfl_down_sync(0xFFFFFFFFu, o0, d);
        o1 += __shfl_down_sync(0xFFFFFFFFu, o1, d);
        o2 += __shfl_down_sync(0xFFFFFFFFu, o2, d);
    }

    __shared__ float red[16][3];
    if ((j & 31) == 0) {
        int w = j >> 5;
        red[w][0] = o0; red[w][1] = o1; red[w][2] = o2;
    }
    __syncthreads();
    if (j < 3) {
        float t = 0.f;
        #pragma unroll
        for (int w = 0; w < 16; ++w) t += red[w][j];
        out[b * 3 + j] = t + b2[j];
    }

    // Re-zero g_x: block b clears its own batch row (3072 floats, float4).
    float4 z4 = make_float4(0.f, 0.f, 0.f, 0.f);
    float* xr = g_x + (size_t)b * K3_;
    #pragma unroll
    for (int it = 0; it < 2; ++it) {
        int e = (it * 512 + j) * 4;          // trailing part: 2 iters not enough
        if (e < K3_) *(float4*)(xr + e) = z4;
    }
    // remaining elements (K3_/4 = 768 float4s; 512 thr * 2 = 1024 >= 768) done.
}

// ---------------------------------------------------------------------------
extern "C" void kernel_launch(void* const* d_in, const int* in_sizes, int n_in,
                              void* d_out, int out_size) {
    const float*        bert  = (const float*)d_in[0];
    const unsigned int* offw  = (const unsigned int*)d_in[1];
    const float*        W1    = (const float*)d_in[2];
    const float*        b1    = (const float*)d_in[3];
    const float*        gamma = (const float*)d_in[4];
    const float*        beta  = (const float*)d_in[5];
    const float*        rmean = (const float*)d_in[6];
    const float*        rvar  = (const float*)d_in[7];
    const float*        W2    = (const float*)d_in[8];
    const float*        b2    = (const float*)d_in[9];
    float* out = (float*)d_out;

    const int gemm_smem = KC_ * 64 * 8 + KC_ * 256 * 4;  // 24 KB + 48 KB
    cudaFuncSetAttribute(gemm1, cudaFuncAttributeMaxDynamicSharedMemorySize,
                         gemm_smem);

    span_partial<<<dim3(B_, NCHUNK), 256>>>(bert, offw);
    gemm1<<<dim3(2, NSLAB), 256, gemm_smem>>>(W1);
    head<<<B_, 512>>>(b1, gamma, beta, rmean, rvar, W2, b2, out);
}

// round 11
// speedup vs baseline: 1.6120x; 1.0837x over previous
#include <cuda_runtime.h>
#include <cuda_bf16.h>
#include <cstdint>

#define B_    64
#define S_    512
#define H_    1024
#define HID_  512
#define K3_   3072   // 3*H
#define EPS_  1e-5f
#define NCHUNK 16    // row chunks per span pass (512/32)
#define CHROWS 32    // rows per chunk
#define KC_   48     // k per smem tile
#define NSLAB 64     // gemm k-slabs (one per kt)

// Scratch (device globals: allocation-free, zero-initialized at load).
// INVARIANT: g_x and g_h are all-zero on entry to kernel_launch; the head
// kernel restores this invariant at the end of every call.
__device__ float g_x[B_ * K3_];                // concat embeddings      (768 KB)
__device__ float g_h[B_ * HID_];               // GEMM accumulator       (128 KB)

// ---------------------------------------------------------------------------
// Inline offset decode: detect int64 vs int32 source.
// ---------------------------------------------------------------------------
__device__ __forceinline__ int off_not64(const unsigned int* __restrict__ raw) {
    __shared__ int flag;
    if (threadIdx.x == 0) flag = 0;
    __syncthreads();
    for (int t = threadIdx.x; t < 160; t += blockDim.x)
        if (raw[2 * t + 1] != 0u) atomicExch(&flag, 1);
    __syncthreads();
    return flag;
}
__device__ __forceinline__ int off_get(const unsigned int* __restrict__ raw,
                                       int not64, int idx) {
    return not64 ? (int)raw[idx] : (int)raw[2 * idx];
}

// ---------------------------------------------------------------------------
// Range sum with 4 independent accumulators (4 LDG.128 in flight per iter).
// ---------------------------------------------------------------------------
__device__ __forceinline__ float4 range_sum(const float* __restrict__ base,
                                            int s0, int s1) {
    float4 a0 = make_float4(0.f, 0.f, 0.f, 0.f);
    float4 a1 = a0, a2 = a0, a3 = a0;
    int s = s0;
    for (; s + 3 <= s1; s += 4) {
        float4 v0 = *(const float4*)(base + (size_t)(s + 0) * H_);
        float4 v1 = *(const float4*)(base + (size_t)(s + 1) * H_);
        float4 v2 = *(const float4*)(base + (size_t)(s + 2) * H_);
        float4 v3 = *(const float4*)(base + (size_t)(s + 3) * H_);
        a0.x += v0.x; a0.y += v0.y; a0.z += v0.z; a0.w += v0.w;
        a1.x += v1.x; a1.y += v1.y; a1.z += v1.z; a1.w += v1.w;
        a2.x += v2.x; a2.y += v2.y; a2.z += v2.z; a2.w += v2.w;
        a3.x += v3.x; a3.y += v3.y; a3.z += v3.z; a3.w += v3.w;
    }
    for (; s <= s1; ++s) {
        float4 v = *(const float4*)(base + (size_t)s * H_);
        a0.x += v.x; a0.y += v.y; a0.z += v.z; a0.w += v.w;
    }
    a0.x += a1.x + a2.x + a3.x;
    a0.y += a1.y + a2.y + a3.y;
    a0.z += a1.z + a2.z + a3.z;
    a0.w += a1.w + a2.w + a3.w;
    return a0;
}

// ---------------------------------------------------------------------------
// Kernel 1: span partial means -> REDG into g_x; pronoun row copy.
// grid (B, NCHUNK=16), 256 thr, float4/thread, 32-row chunks.
// ---------------------------------------------------------------------------
__global__ void span_partial(const float* __restrict__ bert,
                             const unsigned int* __restrict__ raw) {
    int n64 = off_not64(raw);
    int b  = blockIdx.x;
    int z  = blockIdx.y;
    int a0 = off_get(raw, n64, b * 5 + 0), a1 = off_get(raw, n64, b * 5 + 1);
    int c0 = off_get(raw, n64, b * 5 + 2), c1 = off_get(raw, n64, b * 5 + 3);
    int p  = off_get(raw, n64, b * 5 + 4);
    int lo = z * CHROWS, hi = lo + CHROWS - 1;
    int sA0 = max(a0, lo), sA1 = min(a1, hi);
    int sB0 = max(c0, lo), sB1 = min(c1, hi);
    float inva = 1.0f / (float)(a1 - a0 + 1);
    float invb = 1.0f / (float)(c1 - c0 + 1);

    int t = threadIdx.x;
    const float* base = bert + ((size_t)b * S_) * H_ + 4 * t;
    float* xr = g_x + (size_t)b * K3_ + 4 * t;

    if (sA1 >= sA0) {
        float4 acc = range_sum(base, sA0, sA1);
        atomicAdd(xr + 0, acc.x * inva);
        atomicAdd(xr + 1, acc.y * inva);
        atomicAdd(xr + 2, acc.z * inva);
        atomicAdd(xr + 3, acc.w * inva);
    }
    if (sB1 >= sB0) {
        float4 acc = range_sum(base, sB0, sB1);
        atomicAdd(xr + H_ + 0, acc.x * invb);
        atomicAdd(xr + H_ + 1, acc.y * invb);
        atomicAdd(xr + H_ + 2, acc.z * invb);
        atomicAdd(xr + H_ + 3, acc.w * invb);
    }
    // Pronoun row: the chunk that owns row p copies it (plain stores).
    if (p >= lo && p <= hi) {
        float4 v = *(const float4*)(base + (size_t)p * H_);
        *(float4*)(xr + 2 * H_) = v;
    }
}

// ---------------------------------------------------------------------------
// Kernel 2: GEMM x(64x3072) @ W1(3072x512), split-k over 64 kt chunks.
// grid(2 jt x 64 kt) = 128 CTAs, 256 threads. Block tile 64m x 256j x 48k.
// Thread tile 8m x 8j, FFMA2, x broadcast, conflict-free LDS.64 for W.
// Epilogue: RED.E.ADD.F32 into g_h.
// ---------------------------------------------------------------------------
#define FMA2(A, W, X) asm("fma.rn.f32x2 %0, %1, %2, %0;" \
                          : "+l"(A) : "l"(W), "l"(X))

__global__ void __launch_bounds__(256) gemm1(const float* __restrict__ W1) {
    extern __shared__ char smraw[];
    float2* xs2 = (float2*)smraw;                    // [KC_][64]  24 KB
    float*  ws  = (float*)(smraw + KC_ * 64 * 8);    // [KC_][256] 48 KB

    int jt  = blockIdx.x;           // 0..1
    int kt  = blockIdx.y;           // 0..63
    int tid = threadIdx.x;
    int jg  = tid & 31;             // lane: j-pair base
    int mg  = tid >> 5;             // warp: m-group of 8
    int jb  = jt * 256;
    int k0  = kt * KC_;
    int m0  = mg * 8;

    // W1 tile [KC_][256]: coalesced LDG.128, conflict-free STS
    #pragma unroll
    for (int it = 0; it < 12; ++it) {
        int i = it * 256 + tid;
        int r = i >> 6, c = (i & 63) << 2;
        *(float4*)&ws[r * 256 + c] =
            *(const float4*)&W1[(size_t)(k0 + r) * HID_ + jb + c];
    }
    // x tile transposed + duplicated {v,v}: conflict-free STS
    #pragma unroll
    for (int it = 0; it < 3; ++it) {
        int i  = it * 256 + tid;
        int kq = i >> 6;                        // 0..11
        int m  = i & 63;
        float4 v = *(const float4*)&g_x[(size_t)m * K3_ + k0 + kq * 4];
        xs2[(kq * 4 + 0) * 64 + m] = make_float2(v.x, v.x);
        xs2[(kq * 4 + 1) * 64 + m] = make_float2(v.y, v.y);
        xs2[(kq * 4 + 2) * 64 + m] = make_float2(v.z, v.z);
        xs2[(kq * 4 + 3) * 64 + m] = make_float2(v.w, v.w);
    }
    __syncthreads();

    unsigned long long acc[8][4];   // [m][q]  j = jb + 2*jg + 64*q
    #pragma unroll
    for (int m = 0; m < 8; ++m)
        #pragma unroll
        for (int q = 0; q < 4; ++q) acc[m][q] = 0ull;

    const float*  wp = ws + 2 * jg;
    const float2* xp = xs2 + m0;

    // register double-buffer
    unsigned long long cw[4];
    ulonglong2 cx[4];
    #pragma unroll
    for (int q = 0; q < 4; ++q)
        cw[q] = *(const unsigned long long*)(wp + q * 64);
    #pragma unroll
    for (int i = 0; i < 4; ++i)
        cx[i] = *(const ulonglong2*)(xp + i * 2);

    #pragma unroll
    for (int k = 0; k < KC_; ++k) {
        unsigned long long nw[4];
        ulonglong2 nx[4];
        if (k < KC_ - 1) {
            const float*  wn = wp + (k + 1) * 256;
            const float2* xn = xp + (k + 1) * 64;
            #pragma unroll
            for (int q = 0; q < 4; ++q)
                nw[q] = *(const unsigned long long*)(wn + q * 64);
            #pragma unroll
            for (int i = 0; i < 4; ++i)
                nx[i] = *(const ulonglong2*)(xn + i * 2);
        }
        unsigned long long xm[8] = {cx[0].x, cx[0].y, cx[1].x, cx[1].y,
                                    cx[2].x, cx[2].y, cx[3].x, cx[3].y};
        #pragma unroll
        for (int m = 0; m < 8; ++m) {
            FMA2(acc[m][0], cw[0], xm[m]);
            FMA2(acc[m][1], cw[1], xm[m]);
            FMA2(acc[m][2], cw[2], xm[m]);
            FMA2(acc[m][3], cw[3], xm[m]);
        }
        #pragma unroll
        for (int q = 0; q < 4; ++q) cw[q] = nw[q];
        #pragma unroll
        for (int i = 0; i < 4; ++i) cx[i] = nx[i];
    }

    // Epilogue: no-return atomics into g_h (spread addresses)
    #pragma unroll
    for (int m = 0; m < 8; ++m) {
        float* row = &g_h[(m0 + m) * HID_ + jb + 2 * jg];
        #pragma unroll
        for (int q = 0; q < 4; ++q) {
            float2 v = *(float2*)&acc[m][q];
            atomicAdd(row + 64 * q,     v.x);
            atomicAdd(row + 64 * q + 1, v.y);
        }
    }
}

// ---------------------------------------------------------------------------
// Kernel 3: BN + leaky + @W2 + b2 -> out[64][3]; then restore the zero
// invariant on g_h (same thread that read it) and g_x (block-partitioned).
// grid(B), 512 thr.
// ---------------------------------------------------------------------------
__global__ void head(const float* __restrict__ b1,
                     const float* __restrict__ gamma,
                     const float* __restrict__ beta,
                     const float* __restrict__ rmean,
                     const float* __restrict__ rvar,
                     const float* __restrict__ W2,
                     const float* __restrict__ b2,
                     float* __restrict__ out) {
    int b = blockIdx.x;
    int j = threadIdx.x;               // 0..511

    float s  = g_h[b * HID_ + j];
    g_h[b * HID_ + j] = 0.f;           // re-zero own element (same thread)

    float sc = gamma[j] * rsqrtf(rvar[j] + EPS_);
    float h  = (s + b1[j] - rmean[j]) * sc + beta[j];
    h = (h >= 0.f) ? h : 0.01f * h;

    float o0 = h * W2[j * 3 + 0];
    float o1 = h * W2[j * 3 + 1];
    float o2 = h * W2[j * 3 + 2];

    #pragma unroll
    for (int d = 16; d > 0; d >>= 1) {
        o0 += __shfl_down_sync(0xFFFFFFFFu, o0, d);
        o1 += __shfl_down_sync(0xFFFFFFFFu, o1, d);
        o2 += __shfl_down_sync(0xFFFFFFFFu, o2, d);
    }

    __shared__ float red[16][3];
    if ((j & 31) == 0) {
        int w = j >> 5;
        red[w][0] = o0; red[w][1] = o1; red[w][2] = o2;
    }
    __syncthreads();
    if (j < 3) {
        float t = 0.f;
        #pragma unroll
        for (int w = 0; w < 16; ++w) t += red[w][j];
        out[b * 3 + j] = t + b2[j];
    }

    // Re-zero g_x: block b clears its own batch row (3072 floats, float4).
    float4 z4 = make_float4(0.f, 0.f, 0.f, 0.f);
    float* xr = g_x + (size_t)b * K3_;
    #pragma unroll
    for (int it = 0; it < 2; ++it) {
        int e = (it * 512 + j) * 4;
        if (e < K3_) *(float4*)(xr + e) = z4;
    }
}

// ---------------------------------------------------------------------------
extern "C" void kernel_launch(void* const* d_in, const int* in_sizes, int n_in,
                              void* d_out, int out_size) {
    const float*        bert  = (const float*)d_in[0];
    const unsigned int* offw  = (const unsigned int*)d_in[1];
    const float*        W1    = (const float*)d_in[2];
    const float*        b1    = (const float*)d_in[3];
    const float*        gamma = (const float*)d_in[4];
    const float*        beta  = (const float*)d_in[5];
    const float*        rmean = (const float*)d_in[6];
    const float*        rvar  = (const float*)d_in[7];
    const float*        W2    = (const float*)d_in[8];
    const float*        b2    = (const float*)d_in[9];
    float* out = (float*)d_out;

    const int gemm_smem = KC_ * 64 * 8 + KC_ * 256 * 4;  // 24 KB + 48 KB
    cudaFuncSetAttribute(gemm1, cudaFuncAttributeMaxDynamicSharedMemorySize,
                         gemm_smem);

    span_partial<<<dim3(B_, NCHUNK), 256>>>(bert, offw);
    gemm1<<<dim3(2, NSLAB), 256, gemm_smem>>>(W1);
    head<<<B_, 512>>>(b1, gamma, beta, rmean, rvar, W2, b2, out);
}

// round 12
// speedup vs baseline: 1.6139x; 1.0012x over previous
#include <cuda_runtime.h>
#include <cuda_bf16.h>
#include <cstdint>

#define B_    64
#define S_    512
#define H_    1024
#define HID_  512
#define K3_   3072   // 3*H
#define EPS_  1e-5f
#define NCHUNK 16    // row chunks per span pass (512/32)
#define CHROWS 32    // rows per chunk
#define KC_   48     // k per smem tile
#define NSLAB 64     // gemm k-slabs (one per kt)

// Scratch (device globals: allocation-free, zero-initialized at load).
// INVARIANT: g_x and g_h are all-zero on entry to kernel_launch; the head
// kernel restores this invariant at the end of every call.
__device__ float g_x[B_ * K3_];                // concat embeddings      (768 KB)
__device__ float g_h[B_ * HID_];               // GEMM accumulator       (128 KB)
__device__ float g_sink;                       // prefetch sink (never written)

// ---------------------------------------------------------------------------
// Inline offset decode: detect int64 vs int32 source.
// ---------------------------------------------------------------------------
__device__ __forceinline__ int off_not64(const unsigned int* __restrict__ raw) {
    __shared__ int flag;
    if (threadIdx.x == 0) flag = 0;
    __syncthreads();
    for (int t = threadIdx.x; t < 160; t += blockDim.x)
        if (raw[2 * t + 1] != 0u) atomicExch(&flag, 1);
    __syncthreads();
    return flag;
}
__device__ __forceinline__ int off_get(const unsigned int* __restrict__ raw,
                                       int not64, int idx) {
    return not64 ? (int)raw[idx] : (int)raw[2 * idx];
}

// ---------------------------------------------------------------------------
// Range sum with 8 independent LDG.128 in flight per iteration (MLP=8).
// ---------------------------------------------------------------------------
__device__ __forceinline__ float4 range_sum(const float* __restrict__ base,
                                            int s0, int s1) {
    float4 a0 = make_float4(0.f, 0.f, 0.f, 0.f);
    float4 a1 = a0, a2 = a0, a3 = a0;
    int s = s0;
    for (; s + 7 <= s1; s += 8) {
        float4 v0 = *(const float4*)(base + (size_t)(s + 0) * H_);
        float4 v1 = *(const float4*)(base + (size_t)(s + 1) * H_);
        float4 v2 = *(const float4*)(base + (size_t)(s + 2) * H_);
        float4 v3 = *(const float4*)(base + (size_t)(s + 3) * H_);
        float4 v4 = *(const float4*)(base + (size_t)(s + 4) * H_);
        float4 v5 = *(const float4*)(base + (size_t)(s + 5) * H_);
        float4 v6 = *(const float4*)(base + (size_t)(s + 6) * H_);
        float4 v7 = *(const float4*)(base + (size_t)(s + 7) * H_);
        a0.x += v0.x + v4.x; a0.y += v0.y + v4.y;
        a0.z += v0.z + v4.z; a0.w += v0.w + v4.w;
        a1.x += v1.x + v5.x; a1.y += v1.y + v5.y;
        a1.z += v1.z + v5.z; a1.w += v1.w + v5.w;
        a2.x += v2.x + v6.x; a2.y += v2.y + v6.y;
        a2.z += v2.z + v6.z; a2.w += v2.w + v6.w;
        a3.x += v3.x + v7.x; a3.y += v3.y + v7.y;
        a3.z += v3.z + v7.z; a3.w += v3.w + v7.w;
    }
    for (; s + 3 <= s1; s += 4) {
        float4 v0 = *(const float4*)(base + (size_t)(s + 0) * H_);
        float4 v1 = *(const float4*)(base + (size_t)(s + 1) * H_);
        float4 v2 = *(const float4*)(base + (size_t)(s + 2) * H_);
        float4 v3 = *(const float4*)(base + (size_t)(s + 3) * H_);
        a0.x += v0.x; a0.y += v0.y; a0.z += v0.z; a0.w += v0.w;
        a1.x += v1.x; a1.y += v1.y; a1.z += v1.z; a1.w += v1.w;
        a2.x += v2.x; a2.y += v2.y; a2.z += v2.z; a2.w += v2.w;
        a3.x += v3.x; a3.y += v3.y; a3.z += v3.z; a3.w += v3.w;
    }
    for (; s <= s1; ++s) {
        float4 v = *(const float4*)(base + (size_t)s * H_);
        a0.x += v.x; a0.y += v.y; a0.z += v.z; a0.w += v.w;
    }
    a0.x += a1.x + a2.x + a3.x;
    a0.y += a1.y + a2.y + a3.y;
    a0.z += a1.z + a2.z + a3.z;
    a0.w += a1.w + a2.w + a3.w;
    return a0;
}

// ---------------------------------------------------------------------------
// Kernel 1: span partial means -> REDG into g_x; pronoun row copy.
// Also: each block streams its 6 KB share of W1 to warm L2 for gemm1
// (span runs at ~50% DRAM; prefetch rides the spare bandwidth).
// grid (B, NCHUNK=16), 256 thr, float4/thread, 32-row chunks.
// ---------------------------------------------------------------------------
__global__ void span_partial(const float* __restrict__ bert,
                             const unsigned int* __restrict__ raw,
                             const float* __restrict__ W1) {
    int n64 = off_not64(raw);
    int b  = blockIdx.x;
    int z  = blockIdx.y;
    int a0 = off_get(raw, n64, b * 5 + 0), a1 = off_get(raw, n64, b * 5 + 1);
    int c0 = off_get(raw, n64, b * 5 + 2), c1 = off_get(raw, n64, b * 5 + 3);
    int p  = off_get(raw, n64, b * 5 + 4);
    int lo = z * CHROWS, hi = lo + CHROWS - 1;
    int sA0 = max(a0, lo), sA1 = min(a1, hi);
    int sB0 = max(c0, lo), sB1 = min(c1, hi);
    float inva = 1.0f / (float)(a1 - a0 + 1);
    float invb = 1.0f / (float)(c1 - c0 + 1);

    int t = threadIdx.x;
    const float* base = bert + ((size_t)b * S_) * H_ + 4 * t;
    float* xr = g_x + (size_t)b * K3_ + 4 * t;

    // L2-prefetch of this block's W1 slice (6 KB = 384 float4 per block).
    // The sum is kept live via a condition the compiler cannot fold.
    float pf = 0.f;
    {
        int blk = b * NCHUNK + z;                   // 0..1023
        const float4* wseg =
            (const float4*)(W1 + (size_t)blk * (K3_ * HID_ / 1024));
        #pragma unroll
        for (int it = 0; it < 2; ++it) {
            int i = it * 256 + t;
            if (i < 384) {
                float4 w = wseg[i];
                pf += w.x + w.y + w.z + w.w;
            }
        }
    }

    if (sA1 >= sA0) {
        float4 acc = range_sum(base, sA0, sA1);
        atomicAdd(xr + 0, acc.x * inva);
        atomicAdd(xr + 1, acc.y * inva);
        atomicAdd(xr + 2, acc.z * inva);
        atomicAdd(xr + 3, acc.w * inva);
    }
    if (sB1 >= sB0) {
        float4 acc = range_sum(base, sB0, sB1);
        atomicAdd(xr + H_ + 0, acc.x * invb);
        atomicAdd(xr + H_ + 1, acc.y * invb);
        atomicAdd(xr + H_ + 2, acc.z * invb);
        atomicAdd(xr + H_ + 3, acc.w * invb);
    }
    // Pronoun row: the chunk that owns row p copies it (plain stores).
    if (p >= lo && p <= hi) {
        float4 v = *(const float4*)(base + (size_t)p * H_);
        *(float4*)(xr + 2 * H_) = v;
    }
    // Keep the prefetch loads alive (condition is never true for finite data).
    if (pf == 1.2345678e38f) g_sink = pf;
}

// ---------------------------------------------------------------------------
// Kernel 2: GEMM x(64x3072) @ W1(3072x512), split-k over 64 kt chunks.
// grid(2 jt x 64 kt) = 128 CTAs, 256 threads. Block tile 64m x 256j x 48k.
// Thread tile 8m x 8j, FFMA2, x broadcast, conflict-free LDS.64 for W.
// Epilogue: RED.E.ADD.F32 into g_h.
// ---------------------------------------------------------------------------
#define FMA2(A, W, X) asm("fma.rn.f32x2 %0, %1, %2, %0;" \
                          : "+l"(A) : "l"(W), "l"(X))

__global__ void __launch_bounds__(256) gemm1(const float* __restrict__ W1) {
    extern __shared__ char smraw[];
    float2* xs2 = (float2*)smraw;                    // [KC_][64]  24 KB
    float*  ws  = (float*)(smraw + KC_ * 64 * 8);    // [KC_][256] 48 KB

    int jt  = blockIdx.x;           // 0..1
    int kt  = blockIdx.y;           // 0..63
    int tid = threadIdx.x;
    int jg  = tid & 31;             // lane: j-pair base
    int mg  = tid >> 5;             // warp: m-group of 8
    int jb  = jt * 256;
    int k0  = kt * KC_;
    int m0  = mg * 8;

    // W1 tile [KC_][256]: coalesced LDG.128 (L2-warm), conflict-free STS
    #pragma unroll
    for (int it = 0; it < 12; ++it) {
        int i = it * 256 + tid;
        int r = i >> 6, c = (i & 63) << 2;
        *(float4*)&ws[r * 256 + c] =
            *(const float4*)&W1[(size_t)(k0 + r) * HID_ + jb + c];
    }
    // x tile transposed + duplicated {v,v}: conflict-free STS
    #pragma unroll
    for (int it = 0; it < 3; ++it) {
        int i  = it * 256 + tid;
        int kq = i >> 6;                        // 0..11
        int m  = i & 63;
        float4 v = *(const float4*)&g_x[(size_t)m * K3_ + k0 + kq * 4];
        xs2[(kq * 4 + 0) * 64 + m] = make_float2(v.x, v.x);
        xs2[(kq * 4 + 1) * 64 + m] = make_float2(v.y, v.y);
        xs2[(kq * 4 + 2) * 64 + m] = make_float2(v.z, v.z);
        xs2[(kq * 4 + 3) * 64 + m] = make_float2(v.w, v.w);
    }
    __syncthreads();

    unsigned long long acc[8][4];   // [m][q]  j = jb + 2*jg + 64*q
    #pragma unroll
    for (int m = 0; m < 8; ++m)
        #pragma unroll
        for (int q = 0; q < 4; ++q) acc[m][q] = 0ull;

    const float*  wp = ws + 2 * jg;
    const float2* xp = xs2 + m0;

    // register double-buffer
    unsigned long long cw[4];
    ulonglong2 cx[4];
    #pragma unroll
    for (int q = 0; q < 4; ++q)
        cw[q] = *(const unsigned long long*)(wp + q * 64);
    #pragma unroll
    for (int i = 0; i < 4; ++i)
        cx[i] = *(const ulonglong2*)(xp + i * 2);

    #pragma unroll
    for (int k = 0; k < KC_; ++k) {
        unsigned long long nw[4];
        ulonglong2 nx[4];
        if (k < KC_ - 1) {
            const float*  wn = wp + (k + 1) * 256;
            const float2* xn = xp + (k + 1) * 64;
            #pragma unroll
            for (int q = 0; q < 4; ++q)
                nw[q] = *(const unsigned long long*)(wn + q * 64);
            #pragma unroll
            for (int i = 0; i < 4; ++i)
                nx[i] = *(const ulonglong2*)(xn + i * 2);
        }
        unsigned long long xm[8] = {cx[0].x, cx[0].y, cx[1].x, cx[1].y,
                                    cx[2].x, cx[2].y, cx[3].x, cx[3].y};
        #pragma unroll
        for (int m = 0; m < 8; ++m) {
            FMA2(acc[m][0], cw[0], xm[m]);
            FMA2(acc[m][1], cw[1], xm[m]);
            FMA2(acc[m][2], cw[2], xm[m]);
            FMA2(acc[m][3], cw[3], xm[m]);
        }
        #pragma unroll
        for (int q = 0; q < 4; ++q) cw[q] = nw[q];
        #pragma unroll
        for (int i = 0; i < 4; ++i) cx[i] = nx[i];
    }

    // Epilogue: no-return atomics into g_h (spread addresses)
    #pragma unroll
    for (int m = 0; m < 8; ++m) {
        float* row = &g_h[(m0 + m) * HID_ + jb + 2 * jg];
        #pragma unroll
        for (int q = 0; q < 4; ++q) {
            float2 v = *(float2*)&acc[m][q];
            atomicAdd(row + 64 * q,     v.x);
            atomicAdd(row + 64 * q + 1, v.y);
        }
    }
}

// ---------------------------------------------------------------------------
// Kernel 3: BN + leaky + @W2 + b2 -> out[64][3]; then restore the zero
// invariant on g_h (same thread that read it) and g_x (block-partitioned).
// grid(B), 512 thr.
// ---------------------------------------------------------------------------
__global__ void head(const float* __restrict__ b1,
                     const float* __restrict__ gamma,
                     const float* __restrict__ beta,
                     const float* __restrict__ rmean,
                     const float* __restrict__ rvar,
                     const float* __restrict__ W2,
                     const float* __restrict__ b2,
                     float* __restrict__ out) {
    int b = blockIdx.x;
    int j = threadIdx.x;               // 0..511

    float s  = g_h[b * HID_ + j];
    g_h[b * HID_ + j] = 0.f;           // re-zero own element (same thread)

    float sc = gamma[j] * rsqrtf(rvar[j] + EPS_);
    float h  = (s + b1[j] - rmean[j]) * sc + beta[j];
    h = (h >= 0.f) ? h : 0.01f * h;

    float o0 = h * W2[j * 3 + 0];
    float o1 = h * W2[j * 3 + 1];
    float o2 = h * W2[j * 3 + 2];

    #pragma unroll
    for (int d = 16; d > 0; d >>= 1) {
        o0 += __shfl_down_sync(0xFFFFFFFFu, o0, d);
        o1 += __shfl_down_sync(0xFFFFFFFFu, o1, d);
        o2 += __shfl_down_sync(0xFFFFFFFFu, o2, d);
    }

    __shared__ float red[16][3];
    if ((j & 31) == 0) {
        int w = j >> 5;
        red[w][0] = o0; red[w][1] = o1; red[w][2] = o2;
    }
    __syncthreads();
    if (j < 3) {
        float t = 0.f;
        #pragma unroll
        for (int w = 0; w < 16; ++w) t += red[w][j];
        out[b * 3 + j] = t + b2[j];
    }

    // Re-zero g_x: block b clears its own batch row (3072 floats, float4).
    float4 z4 = make_float4(0.f, 0.f, 0.f, 0.f);
    float* xr = g_x + (size_t)b * K3_;
    #pragma unroll
    for (int it = 0; it < 2; ++it) {
        int e = (it * 512 + j) * 4;
        if (e < K3_) *(float4*)(xr + e) = z4;
    }
}

// ---------------------------------------------------------------------------
extern "C" void kernel_launch(void* const* d_in, const int* in_sizes, int n_in,
                              void* d_out, int out_size) {
    const float*        bert  = (const float*)d_in[0];
    const unsigned int* offw  = (const unsigned int*)d_in[1];
    const float*        W1    = (const float*)d_in[2];
    const float*        b1    = (const float*)d_in[3];
    const float*        gamma = (const float*)d_in[4];
    const float*        beta  = (const float*)d_in[5];
    const float*        rmean = (const float*)d_in[6];
    const float*        rvar  = (const float*)d_in[7];
    const float*        W2    = (const float*)d_in[8];
    const float*        b2    = (const float*)d_in[9];
    float* out = (float*)d_out;

    const int gemm_smem = KC_ * 64 * 8 + KC_ * 256 * 4;  // 24 KB + 48 KB
    cudaFuncSetAttribute(gemm1, cudaFuncAttributeMaxDynamicSharedMemorySize,
                         gemm_smem);

    span_partial<<<dim3(B_, NCHUNK), 256>>>(bert, offw, W1);
    gemm1<<<dim3(2, NSLAB), 256, gemm_smem>>>(W1);
    head<<<B_, 512>>>(b1, gamma, beta, rmean, rvar, W2, b2, out);
}